// round 3
// baseline (speedup 1.0000x reference)
#include <cuda_runtime.h>
#include <math_constants.h>

#define N_PTS 16384
#define C_DIM 64
#define K_NN  16
#define NSPLIT 8
#define SLICE (N_PTS / NSPLIT)   // 2048
#define BQ 128                    // queries per block (1 per thread)
#define TN 128                    // db points per smem tile

// Scratch (device globals; no dynamic allocation allowed)
__device__ float g_sq[N_PTS];
__device__ float g_pd[NSPLIT * N_PTS * K_NN];   // partial top-k distances
__device__ int   g_pi[NSPLIT * N_PTS * K_NN];   // partial top-k indices
__device__ int   g_knn[N_PTS * K_NN];           // final knn indices
__device__ float g_A[N_PTS * 256];              // x@(W1-W2)+b
__device__ float g_B[N_PTS * 256];              // x@W2

// ---------------- packed f32x2 helpers ----------------
__device__ __forceinline__ unsigned long long ffma2(unsigned long long a,
                                                    unsigned long long b,
                                                    unsigned long long c) {
    unsigned long long d;
    asm("fma.rn.f32x2 %0, %1, %2, %3;" : "=l"(d) : "l"(a), "l"(b), "l"(c));
    return d;
}
__device__ __forceinline__ unsigned long long pack2(float lo, float hi) {
    unsigned long long p;
    asm("mov.b64 %0, {%1, %2};" : "=l"(p) : "f"(lo), "f"(hi));
    return p;
}
__device__ __forceinline__ float sum2(unsigned long long p) {
    float lo, hi;
    asm("mov.b64 {%0, %1}, %2;" : "=f"(lo), "=f"(hi) : "l"(p));
    return lo + hi;
}

// ---------------- 1) squared norms ----------------
__global__ void sqnorm_kernel(const float* __restrict__ x) {
    int i = blockIdx.x * blockDim.x + threadIdx.x;
    const float4* xr = (const float4*)(x + (long)i * C_DIM);
    float s = 0.f;
#pragma unroll
    for (int t = 0; t < C_DIM / 4; ++t) {
        float4 v = xr[t];
        s += v.x * v.x + v.y * v.y + v.z * v.z + v.w * v.w;
    }
    g_sq[i] = s;
}

// ---------------- 2) feature GEMMs: A = x@(W1-W2)+b, B = x@W2 ----------------
__global__ void feat_gemm_kernel(const float* __restrict__ x,
                                 const float* __restrict__ W,
                                 const float* __restrict__ b) {
    __shared__ float xs[16][C_DIM];
    int col = threadIdx.x;             // 0..255  (output column)
    int row0 = blockIdx.x * 16;
    // load x tile (16 rows x 64 cols = 256 float4), coalesced
    ((float4*)xs)[col] = ((const float4*)(x + (long)row0 * C_DIM))[col];
    __syncthreads();

    float p1[16], p2[16];
#pragma unroll
    for (int r = 0; r < 16; ++r) { p1[r] = 0.f; p2[r] = 0.f; }

#pragma unroll 4
    for (int c = 0; c < C_DIM; ++c) {
        float w1 = __ldg(W + c * 256 + col);
        float w2 = __ldg(W + (C_DIM + c) * 256 + col);
#pragma unroll
        for (int r = 0; r < 16; ++r) {
            float xv = xs[r][c];       // broadcast LDS (uniform across warp)
            p1[r] = fmaf(xv, w1, p1[r]);
            p2[r] = fmaf(xv, w2, p2[r]);
        }
    }
    float bias = __ldg(b + col);
#pragma unroll
    for (int r = 0; r < 16; ++r) {
        g_A[(long)(row0 + r) * 256 + col] = p1[r] - p2[r] + bias;
        g_B[(long)(row0 + r) * 256 + col] = p2[r];
    }
}

// ---------------- 3) KNN (split-K over db), f32x2 packed distances ----------------
__global__ __launch_bounds__(BQ, 4) void knn_part_kernel(const float* __restrict__ x) {
    __shared__ float db_s[TN * C_DIM];
    __shared__ float sq_s[TN];
    int tid = threadIdx.x;
    int q = blockIdx.x * BQ + tid;
    int s0 = blockIdx.y * SLICE;

    // query row in registers as 32 packed f32x2
    unsigned long long q2[C_DIM / 2];
    {
        const float2* xr = (const float2*)(x + (long)q * C_DIM);
#pragma unroll
        for (int t = 0; t < C_DIM / 2; ++t) {
            float2 v = xr[t];
            q2[t] = pack2(v.x, v.y);
        }
    }
    float sqq = g_sq[q];

    float kd[K_NN];
    int   ki[K_NN];
#pragma unroll
    for (int t = 0; t < K_NN; ++t) { kd[t] = CUDART_INF_F; ki[t] = -1; }

    for (int tile = 0; tile < SLICE / TN; ++tile) {
        int base = s0 + tile * TN;
        __syncthreads();
#pragma unroll
        for (int it = 0; it < (TN * C_DIM / 4) / BQ; ++it) {
            int off = it * BQ + tid;
            ((float4*)db_s)[off] = ((const float4*)(x + (long)base * C_DIM))[off];
        }
        sq_s[tid] = g_sq[base + tid];
        __syncthreads();

        for (int j = 0; j < TN; ++j) {
            const unsigned long long* db2 =
                (const unsigned long long*)(db_s + j * C_DIM);
            unsigned long long acc = 0ull;  // packed (+0,+0)
#pragma unroll
            for (int cc = 0; cc < C_DIM / 2; ++cc)
                acc = ffma2(q2[cc], db2[cc], acc);
            float dot = sum2(acc);
            float d = sqq + sq_s[j] - 2.f * dot;
            int col = base + j;
            if (d < kd[K_NN - 1] && col != q) {
                kd[K_NN - 1] = d; ki[K_NN - 1] = col;
#pragma unroll
                for (int t = K_NN - 1; t > 0; --t) {
                    if (kd[t] < kd[t - 1]) {
                        float td = kd[t]; kd[t] = kd[t - 1]; kd[t - 1] = td;
                        int ti = ki[t]; ki[t] = ki[t - 1]; ki[t - 1] = ti;
                    }
                }
            }
        }
    }
    long ob = ((long)blockIdx.y * N_PTS + q) * K_NN;
#pragma unroll
    for (int t = 0; t < K_NN; ++t) { g_pd[ob + t] = kd[t]; g_pi[ob + t] = ki[t]; }
}

// ---------------- 4) merge split-K partial top-k lists ----------------
__global__ void merge_kernel() {
    int q = blockIdx.x * blockDim.x + threadIdx.x;
    float kd[K_NN];
    int   ki[K_NN];
#pragma unroll
    for (int t = 0; t < K_NN; ++t) { kd[t] = CUDART_INF_F; ki[t] = -1; }
    // candidates visited in ascending global index order -> jax tie-break match
    for (int s = 0; s < NSPLIT; ++s) {
        long ob = ((long)s * N_PTS + q) * K_NN;
#pragma unroll
        for (int t2 = 0; t2 < K_NN; ++t2) {
            float d = g_pd[ob + t2];
            int   i = g_pi[ob + t2];
            if (d < kd[K_NN - 1]) {
                kd[K_NN - 1] = d; ki[K_NN - 1] = i;
#pragma unroll
                for (int t = K_NN - 1; t > 0; --t) {
                    if (kd[t] < kd[t - 1]) {
                        float td = kd[t]; kd[t] = kd[t - 1]; kd[t - 1] = td;
                        int ti = ki[t]; ki[t] = ki[t - 1]; ki[t - 1] = ti;
                    }
                }
            }
        }
    }
#pragma unroll
    for (int t = 0; t < K_NN; ++t) g_knn[(long)q * K_NN + t] = ki[t];
}

// ---------------- 5) gather + max + relu + pixel-shuffle scatter ----------------
// out[n][c2] = relu(A[n][c2] + max_k B[knn[n][k]][c2]);  y[(n*4+r)*64+c] = out[n][c*4+r]
__global__ void gather_max_kernel(float* __restrict__ y) {
    int t = threadIdx.x;
    int q = blockIdx.x * 4 + (t >> 6);
    int c = t & 63;                    // thread owns c2 in [4c, 4c+4) = (c, r=0..3)
    const int* idx = g_knn + (long)q * K_NN;
    const float4* Bv = (const float4*)g_B;
    float4 m = make_float4(-CUDART_INF_F, -CUDART_INF_F, -CUDART_INF_F, -CUDART_INF_F);
#pragma unroll
    for (int k = 0; k < K_NN; ++k) {
        int j = __ldg(idx + k);
        float4 bv = Bv[(long)j * 64 + c];
        m.x = fmaxf(m.x, bv.x); m.y = fmaxf(m.y, bv.y);
        m.z = fmaxf(m.z, bv.z); m.w = fmaxf(m.w, bv.w);
    }
    float4 a = ((const float4*)g_A)[(long)q * 64 + c];
    y[((long)q * 4 + 0) * 64 + c] = fmaxf(a.x + m.x, 0.f);
    y[((long)q * 4 + 1) * 64 + c] = fmaxf(a.y + m.y, 0.f);
    y[((long)q * 4 + 2) * 64 + c] = fmaxf(a.z + m.z, 0.f);
    y[((long)q * 4 + 3) * 64 + c] = fmaxf(a.w + m.w, 0.f);
}

extern "C" void kernel_launch(void* const* d_in, const int* in_sizes, int n_in,
                              void* d_out, int out_size) {
    const float* x = (const float*)d_in[0];   // (16384, 64) f32
    const float* W = (const float*)d_in[1];   // (128, 256) f32
    const float* b = (const float*)d_in[2];   // (256,) f32
    float* y = (float*)d_out;                 // (65536, 64) f32

    sqnorm_kernel<<<N_PTS / 256, 256>>>(x);
    feat_gemm_kernel<<<N_PTS / 16, 256>>>(x, W, b);
    knn_part_kernel<<<dim3(N_PTS / BQ, NSPLIT), BQ>>>(x);
    merge_kernel<<<N_PTS / 256, 256>>>();
    gather_max_kernel<<<N_PTS / 4, 256>>>(y);
}